// round 7
// baseline (speedup 1.0000x reference)
#include <cuda_runtime.h>
#include <cstdint>

typedef unsigned long long ull;

#define NB      16
#define NENT    100000
#define NTILES  3125           // NENT / 32
#define GRID    296            // 2 blocks per SM
#define TPB     384            // 12 warps = 3 quads
#define NW      12
#define NQUAD   3
#define BUF_F   4096           // floats per staging buffer (32 rows * 128 f)
// dynamic smem: h 8192 B + 3 quads * 2 bufs * 16384 B = 106496 B
#define SMEM_BYTES (8192 + NQUAD * 2 * BUF_F * 4)

// ---------------- device scratch (allocation-free) ----------------
__device__ float    g_part[NB * GRID];
__device__ unsigned g_ctr;     // tile work queue
__device__ unsigned g_done;    // grid barrier epoch counter (monotonic)

// ---------------- packed f32x2 helpers (sm_103a) ----------------
__device__ __forceinline__ ull add2(ull a, ull b) {
    ull r; asm("add.rn.f32x2 %0,%1,%2;" : "=l"(r) : "l"(a), "l"(b)); return r;
}
__device__ __forceinline__ ull fma2(ull a, ull b, ull c) {
    ull r; asm("fma.rn.f32x2 %0,%1,%2,%3;" : "=l"(r) : "l"(a), "l"(b), "l"(c)); return r;
}
__device__ __forceinline__ ull abs2(ull a) { return a & 0x7FFFFFFF7FFFFFFFull; }
__device__ __forceinline__ ull pk2(float a, float b) {
    ull r; asm("mov.b64 %0,{%1,%2};" : "=l"(r) : "f"(a), "f"(b)); return r;
}
__device__ __forceinline__ float2 upk(ull a) {
    float2 f; asm("mov.b64 {%0,%1},%2;" : "=f"(f.x), "=f"(f.y) : "l"(a)); return f;
}
__device__ __forceinline__ float wsum(float v) {
    #pragma unroll
    for (int o = 16; o; o >>= 1) v += __shfl_xor_sync(0xffffffffu, v, o);
    return v;
}
__device__ __forceinline__ unsigned sm_u32(const void* p) {
    unsigned a;
    asm("{ .reg .u64 t; cvta.to.shared.u64 t, %1; cvt.u32.u64 %0, t; }" : "=r"(a) : "l"(p));
    return a;
}
__device__ __forceinline__ void cpa16(unsigned dst, const void* src) {
    asm volatile("cp.async.cg.shared.global [%0], [%1], 16;" :: "r"(dst), "l"(src));
}
__device__ __forceinline__ void barq(int id) {   // quad barrier: 128 threads
    asm volatile("bar.sync %0, 128;" :: "r"(id) : "memory");
}

// =============== single fused kernel ===============
__global__ void __launch_bounds__(TPB, 2)
k_fused(const float* __restrict__ ent, const float* __restrict__ relemb,
        const int* __restrict__ e1w, const int* __restrict__ relw,
        float* __restrict__ out) {
    extern __shared__ float smf[];
    float*      hs   = smf;                            // 16*128 floats, persistent
    ulonglong2* hs2  = (ulonglong2*)smf;               // [16][32] 16B chunks

    int tid = threadIdx.x, w = tid >> 5, l = tid & 31;
    int q = w >> 2, r = w & 3;                         // quad id, role (b-quarter)

    float* buf0 = smf + 2048 + (q * 2    ) * BUF_F;
    float* buf1 = smf + 2048 + (q * 2 + 1) * BUF_F;
    unsigned bu[2] = { sm_u32(buf0), sm_u32(buf1) };

    __shared__ float    invb[NQUAD][32];
    __shared__ unsigned tsl[NQUAD];
    __shared__ float    sp[NW][4];
    __shared__ float    sinv_s[NB];

    // ---- index width detection (int64 => high words zero) ----
    int odd  = e1w[1] | e1w[3] | e1w[5] | e1w[7] | e1w[9] | e1w[11] | e1w[13] | e1w[15];
    int is64 = (odd == 0);

    // ---- build h = norm(ent[e1[b]]) + norm(rel[rel[b]]) ----
    for (int b = w; b < NB; b += NW) {
        long long ei, ri;
        if (is64) { ei = ((const long long*)e1w)[b]; ri = ((const long long*)relw)[b]; }
        else      { ei = (long long)e1w[b];          ri = (long long)relw[b]; }
        float4 a = ((const float4*)ent)[(size_t)ei * 32 + l];
        float sa = wsum(fmaf(a.x, a.x, fmaf(a.y, a.y, fmaf(a.z, a.z, a.w * a.w))));
        float ia = rsqrtf(fmaxf(sa, 1e-24f));
        float4 c = ((const float4*)relemb)[(size_t)ri * 32 + l];
        float sc = wsum(fmaf(c.x, c.x, fmaf(c.y, c.y, fmaf(c.z, c.z, c.w * c.w))));
        float ic = rsqrtf(fmaxf(sc, 1e-24f));
        float4 h;
        h.x = fmaf(a.x, ia, c.x * ic);
        h.y = fmaf(a.y, ia, c.y * ic);
        h.z = fmaf(a.z, ia, c.z * ic);
        h.w = fmaf(a.w, ia, c.w * ic);
        ((float4*)hs)[b * 32 + l] = h;
    }
    __syncthreads();

    float es[4];
    #pragma unroll
    for (int j = 0; j < 4; j++) es[j] = 0.0f;
    const int bq = r * 4;                              // my b rows: bq..bq+3
    const int bid = q + 1;                             // named barrier id

    // ---- prologue: fetch tile 0, stage into buf 0 ----
    if (r == 0 && l == 0) tsl[q] = atomicAdd(&g_ctr, 1u);
    barq(bid);
    unsigned t = tsl[q];
    int p = 0;
    if (t < (unsigned)NTILES) {
        const char* src = (const char*)ent + ((size_t)t * 32 + r * 8) * 512 + l * 16;
        #pragma unroll
        for (int k = 0; k < 8; k++) {
            int row = r * 8 + k;
            cpa16(bu[0] + row * 512 + (((unsigned)(l ^ (row & 7))) << 4), src + (size_t)k * 512);
        }
    }
    asm volatile("cp.async.commit_group;");

    // =============== phase 1: dist -> exp -> store ===============
    while (t < (unsigned)NTILES) {
        int base = (int)t * 32;

        // fetch next tile index, publish to quad
        if (r == 0 && l == 0) tsl[q] = atomicAdd(&g_ctr, 1u);
        barq(bid);                                     // also: buf p^1 free to overwrite
        unsigned tn = tsl[q];

        // stage tile tn into buf p^1 (each warp: its 8 rows)
        if (tn < (unsigned)NTILES) {
            const char* src = (const char*)ent + ((size_t)tn * 32 + r * 8) * 512 + l * 16;
            unsigned dstb = bu[p ^ 1];
            #pragma unroll
            for (int k = 0; k < 8; k++) {
                int row = r * 8 + k;
                cpa16(dstb + row * 512 + (((unsigned)(l ^ (row & 7))) << 4), src + (size_t)k * 512);
            }
        }
        asm volatile("cp.async.commit_group;");
        asm volatile("cp.async.wait_group 1;");        // tile t resident
        barq(bid);                                     // visible quad-wide

        const float*      bp  = (p ? buf1 : buf0);
        const ulonglong2* bp2 = (const ulonglong2*)bp;

        // inv norms: warp r covers rows r*8..r*8+7, 4 lanes per row
        {
            int row = r * 8 + (l >> 2), piece = l & 3;
            float s0 = 0.f, s1 = 0.f;
            #pragma unroll
            for (int k = 0; k < 8; k += 2) {
                int c0 = (piece * 8 + k)     ^ (row & 7);
                int c1 = (piece * 8 + k + 1) ^ (row & 7);
                float4 v0 = ((const float4*)bp)[row * 32 + c0];
                float4 v1 = ((const float4*)bp)[row * 32 + c1];
                s0 = fmaf(v0.x, v0.x, fmaf(v0.y, v0.y, fmaf(v0.z, v0.z, fmaf(v0.w, v0.w, s0))));
                s1 = fmaf(v1.x, v1.x, fmaf(v1.y, v1.y, fmaf(v1.z, v1.z, fmaf(v1.w, v1.w, s1))));
            }
            float ss = s0 + s1;
            ss += __shfl_xor_sync(0xffffffffu, ss, 1);
            ss += __shfl_xor_sync(0xffffffffu, ss, 2);
            if (piece == 0) invb[q][row] = -rsqrtf(fmaxf(ss, 1e-24f));
        }
        barq(bid);

        float iv = invb[q][l];                         // lane l owns entity base+l
        ull  nI = pk2(iv, iv);
        const int swz = l & 7;

        ull acc0 = 0, acc1 = 0, acc2 = 0, acc3 = 0;
        #pragma unroll 4
        for (int c = 0; c < 32; c++) {                 // 32 chunks of 4 dims
            ulonglong2 x = bp2[l * 32 + (c ^ swz)];    // lane-private, conflict-free
            ulonglong2 h0 = hs2[(bq + 0) * 32 + c];    // uniform -> broadcast
            ulonglong2 h1 = hs2[(bq + 1) * 32 + c];
            ulonglong2 h2 = hs2[(bq + 2) * 32 + c];
            ulonglong2 h3 = hs2[(bq + 3) * 32 + c];
            acc0 = add2(acc0, abs2(fma2(x.x, nI, h0.x)));
            acc1 = add2(acc1, abs2(fma2(x.x, nI, h1.x)));
            acc2 = add2(acc2, abs2(fma2(x.x, nI, h2.x)));
            acc3 = add2(acc3, abs2(fma2(x.x, nI, h3.x)));
            acc0 = add2(acc0, abs2(fma2(x.y, nI, h0.y)));
            acc1 = add2(acc1, abs2(fma2(x.y, nI, h1.y)));
            acc2 = add2(acc2, abs2(fma2(x.y, nI, h2.y)));
            acc3 = add2(acc3, abs2(fma2(x.y, nI, h3.y)));
        }

        // exp + store (dist <= ~34: no max pass), coalesced per b
        {
            int el = base + l;
            float2 f0 = upk(acc0), f1 = upk(acc1), f2 = upk(acc2), f3 = upk(acc3);
            float e0 = __expf(f0.x + f0.y);
            float e1 = __expf(f1.x + f1.y);
            float e2 = __expf(f2.x + f2.y);
            float e3 = __expf(f3.x + f3.y);
            out[(size_t)(bq + 0) * NENT + el] = e0;  es[0] += e0;
            out[(size_t)(bq + 1) * NENT + el] = e1;  es[1] += e1;
            out[(size_t)(bq + 2) * NENT + el] = e2;  es[2] += e2;
            out[(size_t)(bq + 3) * NENT + el] = e3;  es[3] += e3;
        }

        t = tn;
        p ^= 1;
    }

    // ---- warp -> block row sums ----
    #pragma unroll
    for (int j = 0; j < 4; j++) {
        float s = wsum(es[j]);
        if (l == 0) sp[w][j] = s;
    }
    __syncthreads();
    if (tid < NB) {
        int b = tid, rr = b >> 2, j = b & 3;
        float s = 0.f;
        #pragma unroll
        for (int k = 0; k < NQUAD; k++) s += sp[k * 4 + rr][j];
        g_part[b * GRID + blockIdx.x] = s;
    }

    // =============== grid-wide barrier (all 296 blocks co-resident) ===============
    __syncthreads();
    if (tid == 0) {
        __threadfence();
        unsigned old = atomicAdd(&g_done, 1u);
        unsigned target = (old / GRID + 1u) * GRID;
        if (old % GRID == GRID - 1u) g_ctr = 0u;       // reset queue for next replay
        unsigned d;
        do {
            asm volatile("ld.global.acquire.gpu.u32 %0, [%1];" : "=r"(d) : "l"(&g_done));
        } while (d < target);
    }
    __syncthreads();

    // ---- reduce partials -> 1/sum per row ----
    for (int b = w; b < NB; b += NW) {
        float s = 0.f;
        for (int i = l; i < GRID; i += 32) s += g_part[b * GRID + i];
        s = wsum(s);
        if (l == 0) sinv_s[b] = 1.0f / s;
    }
    __syncthreads();

    // =============== phase 2: normalize in place (L2-hot) ===============
    {
        const int total4 = NB * NENT / 4;              // 400000
        const int chunk  = (total4 + GRID - 1) / GRID; // 1352
        int start = blockIdx.x * chunk;
        int end   = min(start + chunk, total4);
        float4* o4 = (float4*)out;
        for (int i = start + tid; i < end; i += TPB) {
            int b = i / (NENT / 4);
            float iv = sinv_s[b];
            float4 v = o4[i];
            v.x *= iv; v.y *= iv; v.z *= iv; v.w *= iv;
            o4[i] = v;
        }
    }
}

// ---------------- launch ----------------
extern "C" void kernel_launch(void* const* d_in, const int* in_sizes, int n_in,
                              void* d_out, int out_size) {
    const int*   e1     = (const int*)d_in[0];
    const int*   rel    = (const int*)d_in[1];
    // d_in[2]=X, d_in[3]=A unused by the forward pass
    const float* ent    = (const float*)d_in[4];
    const float* relemb = (const float*)d_in[5];
    float* out = (float*)d_out;

    cudaFuncSetAttribute(k_fused, cudaFuncAttributeMaxDynamicSharedMemorySize, SMEM_BYTES);
    k_fused<<<GRID, TPB, SMEM_BYTES>>>(ent, relemb, e1, rel, out);
    (void)in_sizes; (void)n_in; (void)out_size;
}

// round 8
// speedup vs baseline: 1.1088x; 1.1088x over previous
#include <cuda_runtime.h>
#include <cstdint>

typedef unsigned long long ull;

#define NB      16
#define NENT    100000
#define NTILES  3125           // NENT / 32
#define GRID    296            // 2 blocks per SM
#define TPB     320            // 10 warps = 5 pairs
#define NW      10
#define NPAIR   5
#define ROWF4   33             // float4 per staged row (32 data + 1 pad -> conflict-free)
#define PAIR_F4 (32 * ROWF4)   // 1056 float4 per pair tile
// dynamic smem: h 8192 B + 5 pairs * 16896 B = 92672 B
#define SMEM_BYTES (8192 + NPAIR * PAIR_F4 * 16)

// ---------------- device scratch (allocation-free) ----------------
__device__ float    g_part[NB * GRID];
__device__ unsigned g_ctr;     // tile work queue
__device__ unsigned g_done;    // grid barrier epoch counter (monotonic)

// ---------------- packed f32x2 helpers (sm_103a) ----------------
__device__ __forceinline__ ull add2(ull a, ull b) {
    ull r; asm("add.rn.f32x2 %0,%1,%2;" : "=l"(r) : "l"(a), "l"(b)); return r;
}
__device__ __forceinline__ ull fma2(ull a, ull b, ull c) {
    ull r; asm("fma.rn.f32x2 %0,%1,%2,%3;" : "=l"(r) : "l"(a), "l"(b), "l"(c)); return r;
}
__device__ __forceinline__ ull abs2(ull a) { return a & 0x7FFFFFFF7FFFFFFFull; }
__device__ __forceinline__ ull pk2(float a, float b) {
    ull r; asm("mov.b64 %0,{%1,%2};" : "=l"(r) : "f"(a), "f"(b)); return r;
}
__device__ __forceinline__ float2 upk(ull a) {
    float2 f; asm("mov.b64 {%0,%1},%2;" : "=f"(f.x), "=f"(f.y) : "l"(a)); return f;
}
__device__ __forceinline__ float wsum(float v) {
    #pragma unroll
    for (int o = 16; o; o >>= 1) v += __shfl_xor_sync(0xffffffffu, v, o);
    return v;
}
__device__ __forceinline__ unsigned sm_u32(const void* p) {
    unsigned a;
    asm("{ .reg .u64 t; cvta.to.shared.u64 t, %1; cvt.u32.u64 %0, t; }" : "=r"(a) : "l"(p));
    return a;
}
__device__ __forceinline__ void cpa16(unsigned dst, const void* src) {
    asm volatile("cp.async.cg.shared.global [%0], [%1], 16;" :: "r"(dst), "l"(src));
}
__device__ __forceinline__ void barp(int id) {   // pair barrier: 64 threads
    asm volatile("bar.sync %0, 64;" :: "r"(id) : "memory");
}

// =============== single fused kernel ===============
__global__ void __launch_bounds__(TPB, 2)
k_fused(const float* __restrict__ ent, const float* __restrict__ relemb,
        const int* __restrict__ e1w, const int* __restrict__ relw,
        float* __restrict__ out) {
    extern __shared__ float smf[];
    float*      hs   = smf;                           // 16*128 floats, persistent
    ulonglong2* hs2  = (ulonglong2*)smf;              // [16][32] 16B chunks

    int tid = threadIdx.x, w = tid >> 5, l = tid & 31;
    int p = w >> 1, role = w & 1;                     // pair id, b-half role

    float4*     xs4  = (float4*)(smf + 2048) + p * PAIR_F4;
    unsigned    xw_u = sm_u32(xs4);
    const float4*     myrow4 = xs4 + l * ROWF4;       // lane l's entity row
    const ulonglong2* myrow2 = (const ulonglong2*)myrow4;

    __shared__ unsigned tsl[NPAIR];
    __shared__ float    sp[NW][8];
    __shared__ float    sinv_s[NB];

    // ---- index width detection (int64 => high words zero) ----
    int odd  = e1w[1] | e1w[3] | e1w[5] | e1w[7] | e1w[9] | e1w[11] | e1w[13] | e1w[15];
    int is64 = (odd == 0);

    // ---- build h = norm(ent[e1[b]]) + norm(rel[rel[b]]) ----
    for (int b = w; b < NB; b += NW) {
        long long ei, ri;
        if (is64) { ei = ((const long long*)e1w)[b]; ri = ((const long long*)relw)[b]; }
        else      { ei = (long long)e1w[b];          ri = (long long)relw[b]; }
        float4 a = ((const float4*)ent)[(size_t)ei * 32 + l];
        float sa = wsum(fmaf(a.x, a.x, fmaf(a.y, a.y, fmaf(a.z, a.z, a.w * a.w))));
        float ia = rsqrtf(fmaxf(sa, 1e-24f));
        float4 c = ((const float4*)relemb)[(size_t)ri * 32 + l];
        float sc = wsum(fmaf(c.x, c.x, fmaf(c.y, c.y, fmaf(c.z, c.z, c.w * c.w))));
        float ic = rsqrtf(fmaxf(sc, 1e-24f));
        float4 h;
        h.x = fmaf(a.x, ia, c.x * ic);
        h.y = fmaf(a.y, ia, c.y * ic);
        h.z = fmaf(a.z, ia, c.z * ic);
        h.w = fmaf(a.w, ia, c.w * ic);
        ((float4*)hs)[b * 32 + l] = h;
    }
    __syncthreads();

    float es[8];
    #pragma unroll
    for (int j = 0; j < 8; j++) es[j] = 0.0f;
    const int bq  = role * 8;                          // my b rows: bq..bq+7
    const int bid = p + 1;                             // named barrier id
    const ulonglong2* hb = hs2 + bq * 32;              // base for my b rows

    // ---- initial tile fetch (role-0 warp publishes to the pair) ----
    if (role == 0 && l == 0) tsl[p] = atomicAdd(&g_ctr, 1u);
    barp(bid);
    unsigned t = tsl[p];

    // =============== phase 1: dist -> exp -> store ===============
    while (t < (unsigned)NTILES) {
        int base = (int)t * 32;

        // stage my role's 16 rows (coalesced 512B rows; lane l copies 16B chunk l)
        {
            const char* src = (const char*)ent + ((size_t)base + role * 16) * 512 + l * 16;
            unsigned    dst = xw_u + (unsigned)((role * 16) * ROWF4 + l) * 16;
            #pragma unroll
            for (int k = 0; k < 16; k++)
                cpa16(dst + k * (ROWF4 * 16), src + (size_t)k * 512);
            asm volatile("cp.async.commit_group;");
        }
        // prefetch next tile index while copies are in flight
        if (role == 0 && l == 0) tsl[p] = atomicAdd(&g_ctr, 1u);
        asm volatile("cp.async.wait_group 0;");
        barp(bid);                                     // both halves staged + tsl visible
        unsigned tn = tsl[p];

        // per-lane sumsq of own entity row (conflict-free, immediate offsets)
        float s0 = 0.f, s1 = 0.f, s2 = 0.f, s3 = 0.f;
        #pragma unroll
        for (int c = 0; c < 32; c += 4) {
            float4 v0 = myrow4[c], v1 = myrow4[c+1], v2 = myrow4[c+2], v3 = myrow4[c+3];
            s0 = fmaf(v0.x, v0.x, fmaf(v0.y, v0.y, fmaf(v0.z, v0.z, fmaf(v0.w, v0.w, s0))));
            s1 = fmaf(v1.x, v1.x, fmaf(v1.y, v1.y, fmaf(v1.z, v1.z, fmaf(v1.w, v1.w, s1))));
            s2 = fmaf(v2.x, v2.x, fmaf(v2.y, v2.y, fmaf(v2.z, v2.z, fmaf(v2.w, v2.w, s2))));
            s3 = fmaf(v3.x, v3.x, fmaf(v3.y, v3.y, fmaf(v3.z, v3.z, fmaf(v3.w, v3.w, s3))));
        }
        float ss  = (s0 + s1) + (s2 + s3);
        float inv = -rsqrtf(fmaxf(ss, 1e-24f));        // diff = fma(x, -inv, h)
        ull nI = pk2(inv, inv);

        ull acc[8];
        #pragma unroll
        for (int j = 0; j < 8; j++) acc[j] = 0ull;

        // 8 groups of 4 chunks: batch x into registers, then pure math
        #pragma unroll 4
        for (int g = 0; g < 8; g++) {
            ull xr[8];
            #pragma unroll
            for (int q = 0; q < 4; q++) {
                ulonglong2 xx = myrow2[g * 4 + q];     // immediate offsets
                xr[2*q]   = xx.x;
                xr[2*q+1] = xx.y;
            }
            #pragma unroll
            for (int q = 0; q < 4; q++) {
                int c = g * 4 + q;
                #pragma unroll
                for (int j = 0; j < 8; j++) {
                    ulonglong2 hh = hb[j * 32 + c];    // uniform -> broadcast, imm offs
                    acc[j] = add2(acc[j], abs2(fma2(xr[2*q],   nI, hh.x)));
                    acc[j] = add2(acc[j], abs2(fma2(xr[2*q+1], nI, hh.y)));
                }
            }
        }

        // exp + store (dist <= ~34: no max pass), coalesced per b
        {
            float* outp = out + (size_t)bq * NENT + base + l;
            #pragma unroll
            for (int j = 0; j < 8; j++) {
                float2 f = upk(acc[j]);
                float e = __expf(f.x + f.y);
                outp[(size_t)j * NENT] = e;
                es[j] += e;
            }
        }

        barp(bid);                                     // pair done reading staging
        t = tn;
    }

    // ---- warp -> block row sums ----
    #pragma unroll
    for (int j = 0; j < 8; j++) {
        float s = wsum(es[j]);
        if (l == 0) sp[w][j] = s;
    }
    __syncthreads();
    if (tid < NB) {
        int b = tid, rr = b >> 3, j = b & 7;
        float s = 0.f;
        #pragma unroll
        for (int k = 0; k < NPAIR; k++) s += sp[2 * k + rr][j];
        g_part[b * GRID + blockIdx.x] = s;
    }

    // =============== grid-wide barrier (all 296 blocks co-resident) ===============
    __syncthreads();
    if (tid == 0) {
        __threadfence();
        unsigned old = atomicAdd(&g_done, 1u);
        unsigned target = (old / GRID + 1u) * GRID;
        if (old % GRID == GRID - 1u) g_ctr = 0u;       // reset queue for next replay
        unsigned d;
        do {
            asm volatile("ld.global.acquire.gpu.u32 %0, [%1];" : "=r"(d) : "l"(&g_done));
        } while (d < target);
    }
    __syncthreads();

    // ---- reduce partials -> 1/sum per row ----
    for (int b = w; b < NB; b += NW) {
        float s = 0.f;
        for (int i = l; i < GRID; i += 32) s += g_part[b * GRID + i];
        s = wsum(s);
        if (l == 0) sinv_s[b] = 1.0f / s;
    }
    __syncthreads();

    // =============== phase 2: normalize in place (L2-hot) ===============
    {
        const int total4 = NB * NENT / 4;              // 400000
        const int chunk  = (total4 + GRID - 1) / GRID; // 1352
        int start = blockIdx.x * chunk;
        int end   = min(start + chunk, total4);
        float4* o4 = (float4*)out;
        for (int i = start + tid; i < end; i += TPB) {
            int b = i / (NENT / 4);
            float iv = sinv_s[b];
            float4 v = o4[i];
            v.x *= iv; v.y *= iv; v.z *= iv; v.w *= iv;
            o4[i] = v;
        }
    }
}

// ---------------- launch ----------------
extern "C" void kernel_launch(void* const* d_in, const int* in_sizes, int n_in,
                              void* d_out, int out_size) {
    const int*   e1     = (const int*)d_in[0];
    const int*   rel    = (const int*)d_in[1];
    // d_in[2]=X, d_in[3]=A unused by the forward pass
    const float* ent    = (const float*)d_in[4];
    const float* relemb = (const float*)d_in[5];
    float* out = (float*)d_out;

    cudaFuncSetAttribute(k_fused, cudaFuncAttributeMaxDynamicSharedMemorySize, SMEM_BYTES);
    k_fused<<<GRID, TPB, SMEM_BYTES>>>(ent, relemb, e1, rel, out);
    (void)in_sizes; (void)n_in; (void)out_size;
}